// round 10
// baseline (speedup 1.0000x reference)
#include <cuda_runtime.h>
#include <cstdint>

// snn_input: integrate-and-fire over T=32 steps, N=4194304 neurons.
//   per step: m += image[t]; spk = m >= 1.0f; m -= 1.0f if spk
// Output: [spikes (T*N, 0/1 float32), final mempot (N float32)].
//
// 1.056 GB irreducible traffic; measured 6.69 TB/s (dram__cycles_active
// 84.4%), L2 only 39% -> DRAM controller is the binding resource, and the
// byte count is exact (no waste). R9: full 32-deep front-batch so each
// thread issues ALL reads before ANY write (longest possible R-phase /
// W-phase run length at the memory controller). occ ~25% is fine (proven
// non-binding at 32%), MLP=32/thread.

static constexpr int TSTEPS = 32;
static constexpr float THRES = 1.0f;

__global__ __launch_bounds__(256) void snn_if_kernel(
    const float4* __restrict__ image,    // [T, N/4] as float4
    const float4* __restrict__ mempot0,  // [N/4]
    float4* __restrict__ out,            // [T*N/4 spikes][N/4 mempot]
    int n4)
{
    int i = blockIdx.x * blockDim.x + threadIdx.x;   // grid covers n4 exactly

    float4 m = __ldcs(&mempot0[i]);

    float4 im[TSTEPS];
    // front-batched loads: 32 independent LDG.E.128.CS in flight
#pragma unroll
    for (int t = 0; t < TSTEPS; t++) {
        im[t] = __ldcs(&image[(size_t)t * n4 + i]);
    }

    // compute + store burst (stores only after all loads issued)
#pragma unroll
    for (int t = 0; t < TSTEPS; t++) {
        m.x += im[t].x; m.y += im[t].y; m.z += im[t].z; m.w += im[t].w;
        float4 s;
        s.x = (m.x >= THRES) ? 1.0f : 0.0f;
        s.y = (m.y >= THRES) ? 1.0f : 0.0f;
        s.z = (m.z >= THRES) ? 1.0f : 0.0f;
        s.w = (m.w >= THRES) ? 1.0f : 0.0f;
        // thres == 1.0 so subtracting s == subtracting s*THRES
        m.x -= s.x; m.y -= s.y; m.z -= s.z; m.w -= s.w;
        __stcs(&out[(size_t)t * n4 + i], s);
    }
    __stcs(&out[(size_t)TSTEPS * n4 + i], m);
}

extern "C" void kernel_launch(void* const* d_in, const int* in_sizes, int n_in,
                              void* d_out, int out_size)
{
    const float4* image   = (const float4*)d_in[0];
    const float4* mempot0 = (const float4*)d_in[1];
    float4*       out     = (float4*)d_out;

    int n  = in_sizes[1];      // 4194304 neurons
    int n4 = n / 4;            // 1048576 float4 lanes (= 4096 * 256 exactly)

    const int threads = 256;
    const int blocks  = n4 / threads;
    snn_if_kernel<<<blocks, threads>>>(image, mempot0, out, n4);
}

// round 11
// speedup vs baseline: 1.0125x; 1.0125x over previous
#include <cuda_runtime.h>
#include <cstdint>

// snn_input: integrate-and-fire over T=32 steps, N=4194304 neurons.
//   per step: m += image[t]; spk = m >= 1.0f; m -= 1.0f if spk
// Output: [spikes (T*N, 0/1 float32), final mempot (N float32)].
//
// FINAL (R8 config). 1.056 GB irreducible traffic, byte-exact at DRAM
// (6689 GB/s x 157.7us = 1.055 GB). dram__cycles_active 84.4% is the
// binding resource; L2 39%, all compute pipes idle. Search bracketed:
//   TBATCH: 8 (~166) / 16 (163.97, best) / 32 (regs 159, occ 11%, 174 -
//           occupancy collapse + per-warp LDG outstanding cap)
//   width: 128-bit best; 256-bit v8.f32 neutral
//   layout: lane-coalesced required (thread-consecutive pairs -> L1 76%,
//           DRAM 53%, 252us)
// Remaining ~15% to spec is DRAM-controller R/W-mix turnaround cost,
// unreachable from SASS.

static constexpr int TSTEPS = 32;
static constexpr int TBATCH = 16;
static constexpr float THRES = 1.0f;

__global__ __launch_bounds__(256) void snn_if_kernel(
    const float4* __restrict__ image,    // [T, N/4] as float4
    const float4* __restrict__ mempot0,  // [N/4]
    float4* __restrict__ out,            // [T*N/4 spikes][N/4 mempot]
    int n4)
{
    int i = blockIdx.x * blockDim.x + threadIdx.x;   // grid covers n4 exactly

    float4 m = __ldcs(&mempot0[i]);

#pragma unroll
    for (int tb = 0; tb < TSTEPS / TBATCH; tb++) {
        float4 im[TBATCH];
        // front-batched loads: 16 independent LDG.E.128.CS in flight
#pragma unroll
        for (int j = 0; j < TBATCH; j++) {
            im[j] = __ldcs(&image[(size_t)(tb * TBATCH + j) * n4 + i]);
        }
        // compute + store burst
#pragma unroll
        for (int j = 0; j < TBATCH; j++) {
            m.x += im[j].x; m.y += im[j].y; m.z += im[j].z; m.w += im[j].w;
            float4 s;
            s.x = (m.x >= THRES) ? 1.0f : 0.0f;
            s.y = (m.y >= THRES) ? 1.0f : 0.0f;
            s.z = (m.z >= THRES) ? 1.0f : 0.0f;
            s.w = (m.w >= THRES) ? 1.0f : 0.0f;
            // thres == 1.0 so subtracting s == subtracting s*THRES
            m.x -= s.x; m.y -= s.y; m.z -= s.z; m.w -= s.w;
            __stcs(&out[(size_t)(tb * TBATCH + j) * n4 + i], s);
        }
    }
    __stcs(&out[(size_t)TSTEPS * n4 + i], m);
}

extern "C" void kernel_launch(void* const* d_in, const int* in_sizes, int n_in,
                              void* d_out, int out_size)
{
    const float4* image   = (const float4*)d_in[0];
    const float4* mempot0 = (const float4*)d_in[1];
    float4*       out     = (float4*)d_out;

    int n  = in_sizes[1];      // 4194304 neurons
    int n4 = n / 4;            // 1048576 float4 lanes (= 4096 * 256 exactly)

    const int threads = 256;
    const int blocks  = n4 / threads;
    snn_if_kernel<<<blocks, threads>>>(image, mempot0, out, n4);
}

// round 12
// speedup vs baseline: 1.0153x; 1.0027x over previous
#include <cuda_runtime.h>
#include <cstdint>

// snn_input: integrate-and-fire over T=32 steps, N=4194304 neurons.
//   per step: m += image[t]; spk = m >= 1.0f; m -= 1.0f if spk
// Output: [spikes (T*N, 0/1 float32), final mempot (N float32)].
//
// R12 (final probe): R8 config with 512-thread CTAs. 1.056 GB irreducible
// traffic, byte-exact at DRAM; dram__cycles_active ~84% binding, L2 39%,
// compute idle. Bracketed search:
//   TBATCH: 8 (~166) / 16 (163.97, best) / 32 (occ 11%, 174)
//   width: 128-bit best; 256-bit neutral
//   layout: lane-coalesced required (thread-consecutive -> 252us)
//   3x identical R8 runs: 163.97-164.06us (sigma < 1us)
// Bigger CTA = 8KB contiguous footprint per stream per CTA (vs 4KB);
// last untested DRAM-locality knob. Same regs/occupancy (4x512 = 8x256).

static constexpr int TSTEPS = 32;
static constexpr int TBATCH = 16;
static constexpr float THRES = 1.0f;

__global__ __launch_bounds__(512) void snn_if_kernel(
    const float4* __restrict__ image,    // [T, N/4] as float4
    const float4* __restrict__ mempot0,  // [N/4]
    float4* __restrict__ out,            // [T*N/4 spikes][N/4 mempot]
    int n4)
{
    int i = blockIdx.x * blockDim.x + threadIdx.x;   // grid covers n4 exactly

    float4 m = __ldcs(&mempot0[i]);

#pragma unroll
    for (int tb = 0; tb < TSTEPS / TBATCH; tb++) {
        float4 im[TBATCH];
        // front-batched loads: 16 independent LDG.E.128.CS in flight
#pragma unroll
        for (int j = 0; j < TBATCH; j++) {
            im[j] = __ldcs(&image[(size_t)(tb * TBATCH + j) * n4 + i]);
        }
        // compute + store burst
#pragma unroll
        for (int j = 0; j < TBATCH; j++) {
            m.x += im[j].x; m.y += im[j].y; m.z += im[j].z; m.w += im[j].w;
            float4 s;
            s.x = (m.x >= THRES) ? 1.0f : 0.0f;
            s.y = (m.y >= THRES) ? 1.0f : 0.0f;
            s.z = (m.z >= THRES) ? 1.0f : 0.0f;
            s.w = (m.w >= THRES) ? 1.0f : 0.0f;
            // thres == 1.0 so subtracting s == subtracting s*THRES
            m.x -= s.x; m.y -= s.y; m.z -= s.z; m.w -= s.w;
            __stcs(&out[(size_t)(tb * TBATCH + j) * n4 + i], s);
        }
    }
    __stcs(&out[(size_t)TSTEPS * n4 + i], m);
}

extern "C" void kernel_launch(void* const* d_in, const int* in_sizes, int n_in,
                              void* d_out, int out_size)
{
    const float4* image   = (const float4*)d_in[0];
    const float4* mempot0 = (const float4*)d_in[1];
    float4*       out     = (float4*)d_out;

    int n  = in_sizes[1];      // 4194304 neurons
    int n4 = n / 4;            // 1048576 float4 lanes (= 2048 * 512 exactly)

    const int threads = 512;
    const int blocks  = n4 / threads;
    snn_if_kernel<<<blocks, threads>>>(image, mempot0, out, n4);
}